// round 16
// baseline (speedup 1.0000x reference)
#include <cuda_runtime.h>

#define NT 256
#define NBATCH 1024
typedef unsigned long long u64;

// X=Y=4, D=6, F_IN=2, F_OUT=10, CX=CY=2, B=1024
// inputs: (1024,4,4,2)  peps: (4,4,2,6,6,6,6)  peps_center: (2,10,6,6,6,6)
// out: (1024,10) float32
//
// All _unit() normalizations cancel under the final row-normalization.
// Three range-keepers folded into the next 216-float node (rsqrt of ss
// accumulated in the producing step; dedicated smem reduction scratch).
// One block per batch (R14 structure: HW wave scheduling beats a static
// persistent split). FFMA2-packed insert/contract steps retained from R15.

// ---------------- f32x2 packed-math helpers ----------------
static __device__ __forceinline__ u64 pk2(float a, float b) {
    u64 r; asm("mov.b64 %0,{%1,%2};" : "=l"(r) : "f"(a), "f"(b)); return r;
}
static __device__ __forceinline__ void fma2(u64& d, u64 a, u64 b) {
    asm("fma.rn.f32x2 %0,%1,%2,%0;" : "+l"(d) : "l"(a), "l"(b));
}

struct Smem {
    float Sa[7776];     // ping
    float Sb[7776];     // pong; Sb[6480..7776) doubles as envtop
    float node[1296];   // node buffer; [0:216)=A slot, [648:864)=B slot; dots at end
    float envbot[1296]; // later reused as W output
    float red[16];      // dedicated reduction scratch
};

// ---------------- dual block reduction ----------------
__device__ __forceinline__ float2 block_reduce2(float a, float b, float* red) {
    #pragma unroll
    for (int o = 16; o; o >>= 1) {
        a += __shfl_xor_sync(0xffffffffu, a, o);
        b += __shfl_xor_sync(0xffffffffu, b, o);
    }
    const int w = threadIdx.x >> 5;
    if ((threadIdx.x & 31) == 0) { red[w] = a; red[8 + w] = b; }
    __syncthreads();
    if (threadIdx.x < 32) {
        float ra = (threadIdx.x < 8) ? red[threadIdx.x] : 0.f;
        float rb = (threadIdx.x < 8) ? red[8 + threadIdx.x] : 0.f;
        #pragma unroll
        for (int o = 4; o; o >>= 1) {
            ra += __shfl_xor_sync(0xffffffffu, ra, o);
            rb += __shfl_xor_sync(0xffffffffu, rb, o);
        }
        if (threadIdx.x == 0) { red[0] = ra; red[1] = rb; }
    }
    __syncthreads();
    return make_float2(red[0], red[1]);
}

// ---------------- register-staged node loaders ----------------
// Standard packed layout: buf[((u*R+r)*Dd+d)*L+l]
template <int I, int J, int U, int R, int Dd, int L>
struct NodeLoad {
    static constexpr int N = U * R * Dd * L;
    static constexpr int Q = (N + NT - 1) / NT;
    float v[Q];
    __device__ __forceinline__ void load(const float* __restrict__ peps,
                                         const float* __restrict__ xs) {
        const float x0 = xs[(I * 4 + J) * 2 + 0];
        const float x1 = xs[(I * 4 + J) * 2 + 1];
        const float* T0 = peps + (size_t)((I * 4 + J) * 2) * 1296;
        const float* T1 = T0 + 1296;
        #pragma unroll
        for (int q = 0; q < Q; ++q) {
            int idx = threadIdx.x + q * NT;
            if (idx < N) {
                int l = idx % L;
                int t = idx / L;
                int d = t % Dd; t /= Dd;
                int r = t % R;
                int u = t / R;
                int g = ((u * 6 + r) * 6 + d) * 6 + l;
                v[q] = fmaf(x0, __ldg(T0 + g), x1 * __ldg(T1 + g));
            }
        }
    }
    __device__ __forceinline__ void store(float* __restrict__ buf) {
        #pragma unroll
        for (int q = 0; q < Q; ++q) {
            int idx = threadIdx.x + q * NT;
            if (idx < N) buf[idx] = v[q];
        }
    }
    __device__ __forceinline__ void store_scaled(float* __restrict__ buf, float s) {
        #pragma unroll
        for (int q = 0; q < Q; ++q) {
            int idx = threadIdx.x + q * NT;
            if (idx < N) buf[idx] = v[q] * s;
        }
    }
};

// N10/N20 in [u][d][r] layout (r contiguous for FFMA2 r-pair packing in insert)
template <int I, int J>
struct NodeLoadDR {
    float v;
    __device__ __forceinline__ void load(const float* __restrict__ peps,
                                         const float* __restrict__ xs) {
        const int idx = threadIdx.x;
        if (idx < 216) {
            const float x0 = xs[(I * 4 + J) * 2 + 0];
            const float x1 = xs[(I * 4 + J) * 2 + 1];
            const float* T0 = peps + (size_t)((I * 4 + J) * 2) * 1296;
            const float* T1 = T0 + 1296;
            const int u = idx / 36, d = (idx / 6) % 6, r = idx % 6;
            const int g = ((u * 6 + r) * 6 + d) * 6;       // l = 0
            v = fmaf(x0, __ldg(T0 + g), x1 * __ldg(T1 + g));
        }
    }
    __device__ __forceinline__ void store_scaled(float* __restrict__ buf, float s) {
        if (threadIdx.x < 216) buf[threadIdx.x] = v * s;
    }
};

// N13 in [u][l][d] layout (d contiguous for FFMA2 a-pair packing in contract_u)
template <int I, int J>
struct NodeLoadLD {
    float v;
    __device__ __forceinline__ void load(const float* __restrict__ peps,
                                         const float* __restrict__ xs) {
        const int idx = threadIdx.x;
        if (idx < 216) {
            const float x0 = xs[(I * 4 + J) * 2 + 0];
            const float x1 = xs[(I * 4 + J) * 2 + 1];
            const float* T0 = peps + (size_t)((I * 4 + J) * 2) * 1296;
            const float* T1 = T0 + 1296;
            const int u = idx / 36, l = (idx / 6) % 6, d = idx % 6;
            const int g = u * 216 + d * 6 + l;             // r = 0 slice
            v = fmaf(x0, __ldg(T0 + g), x1 * __ldg(T1 + g));
        }
    }
    __device__ __forceinline__ void store(float* __restrict__ buf) {
        if (threadIdx.x < 216) buf[threadIdx.x] = v;
    }
};

// Full node in transposed layout TT[u*216 + d*36 + l*6 + r] = Node[u][r][d][l]
template <int I, int J>
struct NodeLoadTT {
    float v[6];
    __device__ __forceinline__ void load(const float* __restrict__ peps,
                                         const float* __restrict__ xs) {
        const float x0 = xs[(I * 4 + J) * 2 + 0];
        const float x1 = xs[(I * 4 + J) * 2 + 1];
        const float* T0 = peps + (size_t)((I * 4 + J) * 2) * 1296;
        const float* T1 = T0 + 1296;
        #pragma unroll
        for (int q = 0; q < 6; ++q) {
            int g = threadIdx.x + q * NT;
            if (g < 1296) v[q] = fmaf(x0, __ldg(T0 + g), x1 * __ldg(T1 + g));
        }
    }
    __device__ __forceinline__ void store(float* __restrict__ buf) {
        #pragma unroll
        for (int q = 0; q < 6; ++q) {
            int g = threadIdx.x + q * NT;
            if (g < 1296) {
                int l = g % 6, d = (g / 6) % 6, r = (g / 36) % 6, u = g / 216;
                buf[u * 216 + d * 36 + l * 6 + r] = v[q];
            }
        }
    }
};

// ---------------- step bodies (NO internal sync) ----------------

template <int SA, int SR>
__device__ __forceinline__ void step6_body(const float* __restrict__ Sin,
                                           float* __restrict__ Sout,
                                           const float* __restrict__ T) {
    const int t = threadIdx.x;
    if (t < 216) {
        const int m = t / 36, a = (t / 6) % 6, r = t % 6;
        const float* sp = Sin + m * 6;
        const float* tp = T + a * SA + r * SR;
        float acc = 0.f;
        #pragma unroll
        for (int x = 0; x < 6; ++x) acc = fmaf(sp[x], tp[x], acc);
        Sout[t] = acc;
    }
}

template <int SA, int SR>
__device__ __forceinline__ void step36_body(const float* __restrict__ Sin,
                                            float* __restrict__ Sout,
                                            const float* __restrict__ T) {
    const int t = threadIdx.x;
    if (t < 216) {
        const int m = t / 6, a = t % 6;
        float sv[6];
        const float2* sp = reinterpret_cast<const float2*>(Sin + m * 6);
        #pragma unroll
        for (int q = 0; q < 3; ++q) { float2 v = sp[q]; sv[q*2] = v.x; sv[q*2+1] = v.y; }
        float acc[6];
        #pragma unroll
        for (int r = 0; r < 6; ++r) {
            const float2* tp = reinterpret_cast<const float2*>(T + a * SA + r * SR);
            float s = 0.f;
            #pragma unroll
            for (int q = 0; q < 3; ++q) {
                float2 v = tp[q];
                s = fmaf(sv[q*2], v.x, s); s = fmaf(sv[q*2+1], v.y, s);
            }
            acc[r] = s;
        }
        float2* op = reinterpret_cast<float2*>(Sout + t * 6);
        #pragma unroll
        for (int q = 0; q < 3; ++q) op[q] = make_float2(acc[q*2], acc[q*2+1]);
    }
}

__device__ __forceinline__ float stepX6R1_body(const float* __restrict__ Sin,
                                               float* __restrict__ Sout,
                                               const float* __restrict__ T) {
    const int m = threadIdx.x;
    float ss = 0.f;
    if (m < 216) {
        float sv[6];
        const float2* sp = reinterpret_cast<const float2*>(Sin + m * 6);
        #pragma unroll
        for (int q = 0; q < 3; ++q) { float2 v = sp[q]; sv[q*2] = v.x; sv[q*2+1] = v.y; }
        float tt[36];
        const float4* p = reinterpret_cast<const float4*>(T);
        #pragma unroll
        for (int q = 0; q < 9; ++q) { float4 v = p[q]; tt[q*4]=v.x; tt[q*4+1]=v.y; tt[q*4+2]=v.z; tt[q*4+3]=v.w; }
        float acc[6];
        #pragma unroll
        for (int a = 0; a < 6; ++a) {
            float s = 0.f;
            #pragma unroll
            for (int x = 0; x < 6; ++x) s = fmaf(sv[x], tt[a*6+x], s);
            acc[a] = s;
            ss = fmaf(s, s, ss);
        }
        float2* op = reinterpret_cast<float2*>(Sout + m * 6);
        #pragma unroll
        for (int q = 0; q < 3; ++q) op[q] = make_float2(acc[q*2], acc[q*2+1]);
    }
    return ss;
}

// insert with [u][d][r] node: out[m*36 + a*6 + r] = sum_u Sin[u*216+m] * T[u*36 + a*6 + r]
__device__ __forceinline__ void insert_body2(const float* __restrict__ Sin,
                                             float* __restrict__ Sout,
                                             const float* __restrict__ Tdr) {
    const int m = threadIdx.x;
    if (m < 216) {
        u64 acc[18];
        #pragma unroll
        for (int i = 0; i < 18; ++i) acc[i] = 0ull;
        #pragma unroll
        for (int u = 0; u < 6; ++u) {
            const float s = Sin[u * 216 + m];
            const u64 s2 = pk2(s, s);
            const ulonglong2* tp = reinterpret_cast<const ulonglong2*>(Tdr + u * 36);  // broadcast
            #pragma unroll
            for (int q = 0; q < 9; ++q) {
                ulonglong2 w = tp[q];
                fma2(acc[q*2], s2, w.x); fma2(acc[q*2+1], s2, w.y);
            }
        }
        ulonglong2* op = reinterpret_cast<ulonglong2*>(Sout + m * 36);
        #pragma unroll
        for (int q = 0; q < 9; ++q) op[q] = make_ulonglong2(acc[q*2], acc[q*2+1]);
    }
}

// contract_u with [u][l][d] node: out[m*6+a] = sum_{u,x} Sin[(u*216+m)*6+x] * T[u*36 + x*6 + a]
__device__ __forceinline__ float contract_u_body2(const float* __restrict__ Sin,
                                                  float* __restrict__ Sout,
                                                  const float* __restrict__ Tld) {
    const int m = threadIdx.x;
    float ss = 0.f;
    if (m < 216) {
        u64 acc[3] = {0ull, 0ull, 0ull};
        #pragma unroll
        for (int u = 0; u < 6; ++u) {
            float sv[6];
            const float2* sp = reinterpret_cast<const float2*>(Sin + (u * 216 + m) * 6);
            #pragma unroll
            for (int q = 0; q < 3; ++q) { float2 v = sp[q]; sv[q*2] = v.x; sv[q*2+1] = v.y; }
            const u64* tp = reinterpret_cast<const u64*>(Tld + u * 36);  // broadcast
            #pragma unroll
            for (int x = 0; x < 6; ++x) {
                const u64 s2 = pk2(sv[x], sv[x]);
                fma2(acc[0], s2, tp[x*3+0]); fma2(acc[1], s2, tp[x*3+1]); fma2(acc[2], s2, tp[x*3+2]);
            }
        }
        #pragma unroll
        for (int q = 0; q < 3; ++q) {
            float2 f = *reinterpret_cast<float2*>(&acc[q]);
            ss = fmaf(f.x, f.x, ss); ss = fmaf(f.y, f.y, ss);
        }
        u64* op = reinterpret_cast<u64*>(Sout + m * 6);
        op[0] = acc[0]; op[1] = acc[1]; op[2] = acc[2];
    }
    return ss;
}

__device__ __forceinline__ void cstep_full_tt_body(const float* __restrict__ Sin,
                                                   float* __restrict__ Sout,
                                                   const float* __restrict__ TT) {
    const int t = threadIdx.x;
    if (t < 216) {
        const int mg = t / 6, a = t % 6;
        u64 acc[18];
        #pragma unroll
        for (int i = 0; i < 18; ++i) acc[i] = 0ull;
        #pragma unroll
        for (int u = 0; u < 6; ++u) {
            const float* sb = Sin + u * 1296 + mg * 36;
            const ulonglong2* tb = reinterpret_cast<const ulonglong2*>(TT + u * 216 + a * 36);
            #pragma unroll
            for (int xp = 0; xp < 3; ++xp) {
                ulonglong2 w0 = tb[xp*3], w1 = tb[xp*3+1], w2 = tb[xp*3+2];
                const u64 te0 = w0.x, te1 = w0.y, te2 = w1.x;
                const u64 to0 = w1.y, to1 = w2.x, to2 = w2.y;
                #pragma unroll
                for (int mi = 0; mi < 6; ++mi) {
                    const float2 sv = *reinterpret_cast<const float2*>(sb + mi * 6 + xp * 2);
                    const u64 s0 = pk2(sv.x, sv.x);
                    const u64 s1 = pk2(sv.y, sv.y);
                    fma2(acc[mi*3+0], s0, te0); fma2(acc[mi*3+1], s0, te1); fma2(acc[mi*3+2], s0, te2);
                    fma2(acc[mi*3+0], s1, to0); fma2(acc[mi*3+1], s1, to1); fma2(acc[mi*3+2], s1, to2);
                }
            }
        }
        float* ob = Sout + mg * 216 + a * 6;
        #pragma unroll
        for (int mi = 0; mi < 6; ++mi) {
            u64* op = reinterpret_cast<u64*>(ob + mi * 36);
            op[0] = acc[mi*3]; op[1] = acc[mi*3+1]; op[2] = acc[mi*3+2];
        }
    }
}

__global__ void __launch_bounds__(NT, 3)
peps_kernel(const float* __restrict__ inp, const float* __restrict__ peps,
            const float* __restrict__ pc, float* __restrict__ out) {
    extern __shared__ __align__(16) char smem_raw[];
    Smem& S = *reinterpret_cast<Smem*>(smem_raw);
    const int batch = blockIdx.x;
    const float* xs = inp + batch * 32;
    float* const ENVTOP = S.Sb + 6480;
    float* const NA = S.node;         // slot A
    float* const NB = S.node + 648;   // slot B
    float* const DOTS = S.node;       // dead at final
    float* const RED = S.red;

    // ---- prefetch N01,N31; inline N00 -> Sa[0:36], N30 -> Sa[3888:3924] ----
    NodeLoad<0, 1, 1, 6, 6, 6> stA; stA.load(peps, xs);
    NodeLoad<3, 1, 6, 6, 1, 6> stB; stB.load(peps, xs);
    if (threadIdx.x < 36) {
        const int d = threadIdx.x / 6, r = threadIdx.x % 6;
        const int g = (r * 6 + d) * 6;
        const float* T0 = peps;
        const float* T1 = T0 + 1296;
        S.Sa[threadIdx.x] = fmaf(xs[0], __ldg(T0 + g), xs[1] * __ldg(T1 + g));
    } else if (threadIdx.x >= 64 && threadIdx.x < 100) {
        const int tt = threadIdx.x - 64;
        const int g = tt * 36;                      // (u*6+r)*36
        const float* T0 = peps + (size_t)24 * 1296; // (3,0) pair
        const float* T1 = T0 + 1296;
        S.Sa[3888 + tt] = fmaf(xs[24], __ldg(T0 + g), xs[25] * __ldg(T1 + g));
    }
    __syncthreads();

    // ============ fused row0 + row3 boundary chains ============
    stA.store(NA); stB.store(NB);
    NodeLoad<0, 2, 1, 6, 6, 6> stA2; stA2.load(peps, xs);
    NodeLoad<3, 2, 6, 6, 1, 6> stB2; stB2.load(peps, xs);
    __syncthreads();
    step6_body<6, 36>(S.Sa, S.Sb, NA);               // row0 -> Sb[0:216]
    step6_body<36, 6>(S.Sa + 3888, S.Sb + 3888, NB); // row3 -> Sb[3888:4104]
    __syncthreads();
    stA2.store(NA); stB2.store(NB);
    NodeLoad<0, 3, 1, 1, 6, 6> stA3; stA3.load(peps, xs);
    NodeLoad<3, 3, 6, 1, 1, 6> stB3; stB3.load(peps, xs);
    __syncthreads();
    step36_body<6, 36>(S.Sb, S.Sa, NA);
    step36_body<36, 6>(S.Sb + 3888, S.Sa + 3888, NB);
    __syncthreads();
    stA3.store(NA); stB3.store(NB);
    NodeLoadDR<1, 0> st10; st10.load(peps, xs);
    __syncthreads();
    float ss0 = stepX6R1_body(S.Sa, S.Sb, NA);           // row0 env -> Sb[0:1296]
    float ss3 = stepX6R1_body(S.Sa + 3888, S.envbot, NB);// env_bot -> envbot
    const float2 iv = block_reduce2(ss0, ss3, RED);
    const float inv0 = rsqrtf(iv.x);
    const float inv3 = rsqrtf(iv.y);

    // ============ Row 1 ============
    st10.store_scaled(NA, inv0);                         // [u][d][r] layout
    NodeLoadTT<1, 1> st11; st11.load(peps, xs);
    __syncthreads();
    insert_body2(S.Sb, S.Sa, NA);                        // -> 7776
    __syncthreads();
    st11.store(S.node);
    NodeLoadTT<1, 2> st12; st12.load(peps, xs);
    __syncthreads();
    cstep_full_tt_body(S.Sa, S.Sb, S.node);              // N11
    __syncthreads();
    st12.store(S.node);
    NodeLoadLD<1, 3> st13; st13.load(peps, xs);
    __syncthreads();
    cstep_full_tt_body(S.Sb, S.Sa, S.node);              // N12
    __syncthreads();
    st13.store(NA);                                      // [u][l][d] layout
    NodeLoadDR<2, 0> st20; st20.load(peps, xs);
    __syncthreads();
    float sst = contract_u_body2(S.Sa, ENVTOP, NA);      // env_top (Sb tail)
    const float2 ivt = block_reduce2(sst, 0.f, RED);
    const float inv_top = rsqrtf(ivt.x);

    // ============ Row 2 (j=0,1) ============
    st20.store_scaled(NA, inv_top);                      // [u][d][r] layout
    NodeLoadTT<2, 1> st21; st21.load(peps, xs);
    __syncthreads();
    insert_body2(ENVTOP, S.Sa, NA);                      // -> 7776
    __syncthreads();
    st21.store(S.node);
    NodeLoad<2, 3, 6, 1, 6, 6> st23; st23.load(peps, xs);
    __syncthreads();
    cstep_full_tt_body(S.Sa, S.Sb, S.node);              // N21 -> S1 in Sb
    __syncthreads();
    st23.store_scaled(NA, inv3);                         // N23, range-keeper folded
    __syncthreads();

    // ============ E step: thread-per-k, FFMA2 over r ============
    // E[k*36 + d2*6 + r2] = sum_d3 envbot[d0,d1,d2,d3]*n23[u3,d3,r2], k=u3*36+d0*6+d1
    {
        const int t = threadIdx.x;
        if (t < 216) {
            const int u3 = t / 36, d0 = (t / 6) % 6, d1 = t % 6;
            u64 acc[18];
            #pragma unroll
            for (int i = 0; i < 18; ++i) acc[i] = 0ull;
            #pragma unroll
            for (int d3 = 0; d3 < 6; ++d3) {
                const u64* np = reinterpret_cast<const u64*>(NA + u3 * 36 + d3 * 6);
                const u64 n0 = np[0], n1 = np[1], n2v = np[2];
                const float* ebp = S.envbot + d0 * 216 + d1 * 36 + d3;
                #pragma unroll
                for (int d2 = 0; d2 < 6; ++d2) {
                    const float e = ebp[d2 * 6];
                    const u64 e2 = pk2(e, e);
                    fma2(acc[d2*3+0], e2, n0); fma2(acc[d2*3+1], e2, n1); fma2(acc[d2*3+2], e2, n2v);
                }
            }
            u64* op = reinterpret_cast<u64*>(S.Sa + t * 36);
            #pragma unroll
            for (int i = 0; i < 18; ++i) op[i] = acc[i];
        }
        __syncthreads();
    }

    // ============ W step: thread-per-(u,d,r), FFMA2 over l ============
    // W[u*216+r*36+d*6+l] = sum_k S1[u*1296+k*6+l] * E[k*36+d*6+r]  -> envbot
    {
        const int t = threadIdx.x;
        if (t < 216) {
            const int u = t / 36, d = (t / 6) % 6, r = t % 6;
            u64 acc0 = 0ull, acc1 = 0ull, acc2v = 0ull;
            const ulonglong2* sp = reinterpret_cast<const ulonglong2*>(S.Sb + u * 1296);
            const float* ep = S.Sa + d * 6 + r;
            #pragma unroll 4
            for (int kk = 0; kk < 108; ++kk) {
                const ulonglong2 q0 = sp[kk*3], q1 = sp[kk*3+1], q2 = sp[kk*3+2];
                const u64 e02 = pk2(ep[kk * 72], ep[kk * 72]);
                const u64 e12 = pk2(ep[kk * 72 + 36], ep[kk * 72 + 36]);
                fma2(acc0, q0.x, e02); fma2(acc1, q0.y, e02); fma2(acc2v, q1.x, e02);
                fma2(acc0, q1.y, e12); fma2(acc1, q2.x, e12); fma2(acc2v, q2.y, e12);
            }
            u64* op = reinterpret_cast<u64*>(S.envbot + u * 216 + r * 36 + d * 6);
            op[0] = acc0; op[1] = acc1; op[2] = acc2v;
        }
        __syncthreads();
    }

    // ============ final: out[o] ∝ sum_p x_p * <Tc[p,o,:], W> ============
    {
        const int w = threadIdx.x >> 5, lane = threadIdx.x & 31;
        const float4* wv = reinterpret_cast<const float4*>(S.envbot);
        for (int po = w; po < 20; po += 8) {
            const float4* tc = reinterpret_cast<const float4*>(pc + (size_t)po * 1296);
            float s = 0.f;
            for (int g = lane; g < 324; g += 32) {
                float4 a = __ldg(tc + g), v = wv[g];
                s = fmaf(a.x, v.x, s); s = fmaf(a.y, v.y, s);
                s = fmaf(a.z, v.z, s); s = fmaf(a.w, v.w, s);
            }
            #pragma unroll
            for (int o = 16; o; o >>= 1) s += __shfl_xor_sync(0xffffffffu, s, o);
            if (lane == 0) DOTS[po] = s;
        }
        __syncthreads();
        if (threadIdx.x == 0) {
            const float x0 = xs[(2 * 4 + 2) * 2 + 0];
            const float x1 = xs[(2 * 4 + 2) * 2 + 1];
            float raw[10];
            float m = 0.f;
            #pragma unroll
            for (int o = 0; o < 10; ++o) {
                raw[o] = fmaf(x0, DOTS[o], x1 * DOTS[10 + o]);
                m = fmaxf(m, fabsf(raw[o]));
            }
            const float im = 1.0f / m;
            float ss = 0.f;
            #pragma unroll
            for (int o = 0; o < 10; ++o) { const float v = raw[o] * im; ss += v * v; }
            const float inv = rsqrtf(ss) * im;
            #pragma unroll
            for (int o = 0; o < 10; ++o) out[batch * 10 + o] = raw[o] * inv;
        }
    }
}

extern "C" void kernel_launch(void* const* d_in, const int* in_sizes, int n_in,
                              void* d_out, int out_size) {
    const float *inp = nullptr, *peps = nullptr, *pc = nullptr;
    for (int i = 0; i < n_in; ++i) {
        if (in_sizes[i] == 1024 * 4 * 4 * 2)      inp  = (const float*)d_in[i];
        else if (in_sizes[i] == 4 * 4 * 2 * 1296) peps = (const float*)d_in[i];
        else if (in_sizes[i] == 2 * 10 * 1296)    pc   = (const float*)d_in[i];
    }
    const int smem = (int)sizeof(Smem);   // 72,640 B -> 3 blocks/SM
    cudaFuncSetAttribute(peps_kernel, cudaFuncAttributeMaxDynamicSharedMemorySize, smem);
    peps_kernel<<<NBATCH, NT, smem>>>(inp, peps, pc, (float*)d_out);
}

// round 17
// speedup vs baseline: 1.5662x; 1.5662x over previous
#include <cuda_runtime.h>

#define NT 256
typedef unsigned long long u64;

// X=Y=4, D=6, F_IN=2, F_OUT=10, CX=CY=2, B=1024
// inputs: (1024,4,4,2)  peps: (4,4,2,6,6,6,6)  peps_center: (2,10,6,6,6,6)
// out: (1024,10) float32
//
// All _unit() normalizations cancel under the final row-normalization
// (positive per-batch scalars on a multilinear network). Three range-keepers
// remain: ss accumulated in the producing step, reduced via a DEDICATED smem
// scratch, rsqrt folded into the NEXT 216-float node tensor. Row-0 and row-3
// boundary chains fused (independent, identically shaped).
// NOTE: packed-FFMA2 insert/contract variants caused ptxas spills in
// straight-line form (R16: 164us, L1 79%, alu 12%) — keep unpacked here.

// ---------------- f32x2 packed-math helpers ----------------
static __device__ __forceinline__ u64 pk2(float a, float b) {
    u64 r; asm("mov.b64 %0,{%1,%2};" : "=l"(r) : "f"(a), "f"(b)); return r;
}
static __device__ __forceinline__ void fma2(u64& d, u64 a, u64 b) {
    asm("fma.rn.f32x2 %0,%1,%2,%0;" : "+l"(d) : "l"(a), "l"(b));
}

struct Smem {
    float Sa[7776];     // ping
    float Sb[7776];     // pong; Sb[6480..7776) doubles as envtop
    float node[1296];   // node buffer; [0:216)=A slot, [648:864)=B slot; dots at end
    float envbot[1296]; // later reused as W output
    float red[16];      // dedicated reduction scratch
};

// ---------------- dual block reduction ----------------
__device__ __forceinline__ float2 block_reduce2(float a, float b, float* red) {
    #pragma unroll
    for (int o = 16; o; o >>= 1) {
        a += __shfl_xor_sync(0xffffffffu, a, o);
        b += __shfl_xor_sync(0xffffffffu, b, o);
    }
    const int w = threadIdx.x >> 5;
    if ((threadIdx.x & 31) == 0) { red[w] = a; red[8 + w] = b; }
    __syncthreads();
    if (threadIdx.x < 32) {
        float ra = (threadIdx.x < 8) ? red[threadIdx.x] : 0.f;
        float rb = (threadIdx.x < 8) ? red[8 + threadIdx.x] : 0.f;
        #pragma unroll
        for (int o = 4; o; o >>= 1) {
            ra += __shfl_xor_sync(0xffffffffu, ra, o);
            rb += __shfl_xor_sync(0xffffffffu, rb, o);
        }
        if (threadIdx.x == 0) { red[0] = ra; red[1] = rb; }
    }
    __syncthreads();
    return make_float2(red[0], red[1]);
}

// ---------------- register-staged node loaders ----------------
// Standard packed layout: buf[((u*R+r)*Dd+d)*L+l]
template <int I, int J, int U, int R, int Dd, int L>
struct NodeLoad {
    static constexpr int N = U * R * Dd * L;
    static constexpr int Q = (N + NT - 1) / NT;
    float v[Q];
    __device__ __forceinline__ void load(const float* __restrict__ peps,
                                         const float* __restrict__ xs) {
        const float x0 = xs[(I * 4 + J) * 2 + 0];
        const float x1 = xs[(I * 4 + J) * 2 + 1];
        const float* T0 = peps + (size_t)((I * 4 + J) * 2) * 1296;
        const float* T1 = T0 + 1296;
        #pragma unroll
        for (int q = 0; q < Q; ++q) {
            int idx = threadIdx.x + q * NT;
            if (idx < N) {
                int l = idx % L;
                int t = idx / L;
                int d = t % Dd; t /= Dd;
                int r = t % R;
                int u = t / R;
                int g = ((u * 6 + r) * 6 + d) * 6 + l;
                v[q] = fmaf(x0, __ldg(T0 + g), x1 * __ldg(T1 + g));
            }
        }
    }
    __device__ __forceinline__ void store(float* __restrict__ buf) {
        #pragma unroll
        for (int q = 0; q < Q; ++q) {
            int idx = threadIdx.x + q * NT;
            if (idx < N) buf[idx] = v[q];
        }
    }
    __device__ __forceinline__ void store_scaled(float* __restrict__ buf, float s) {
        #pragma unroll
        for (int q = 0; q < Q; ++q) {
            int idx = threadIdx.x + q * NT;
            if (idx < N) buf[idx] = v[q] * s;
        }
    }
};

// Full node in transposed layout TT[u*216 + d*36 + l*6 + r] = Node[u][r][d][l]
template <int I, int J>
struct NodeLoadTT {
    float v[6];
    __device__ __forceinline__ void load(const float* __restrict__ peps,
                                         const float* __restrict__ xs) {
        const float x0 = xs[(I * 4 + J) * 2 + 0];
        const float x1 = xs[(I * 4 + J) * 2 + 1];
        const float* T0 = peps + (size_t)((I * 4 + J) * 2) * 1296;
        const float* T1 = T0 + 1296;
        #pragma unroll
        for (int q = 0; q < 6; ++q) {
            int g = threadIdx.x + q * NT;
            if (g < 1296) v[q] = fmaf(x0, __ldg(T0 + g), x1 * __ldg(T1 + g));
        }
    }
    __device__ __forceinline__ void store(float* __restrict__ buf) {
        #pragma unroll
        for (int q = 0; q < 6; ++q) {
            int g = threadIdx.x + q * NT;
            if (g < 1296) {
                int l = g % 6, d = (g / 6) % 6, r = (g / 36) % 6, u = g / 216;
                buf[u * 216 + d * 36 + l * 6 + r] = v[q];
            }
        }
    }
};

// ---------------- step bodies (NO internal sync) ----------------

template <int SA, int SR>
__device__ __forceinline__ void step6_body(const float* __restrict__ Sin,
                                           float* __restrict__ Sout,
                                           const float* __restrict__ T) {
    const int t = threadIdx.x;
    if (t < 216) {
        const int m = t / 36, a = (t / 6) % 6, r = t % 6;
        const float* sp = Sin + m * 6;
        const float* tp = T + a * SA + r * SR;
        float acc = 0.f;
        #pragma unroll
        for (int x = 0; x < 6; ++x) acc = fmaf(sp[x], tp[x], acc);
        Sout[t] = acc;
    }
}

template <int SA, int SR>
__device__ __forceinline__ void step36_body(const float* __restrict__ Sin,
                                            float* __restrict__ Sout,
                                            const float* __restrict__ T) {
    const int t = threadIdx.x;
    if (t < 216) {
        const int m = t / 6, a = t % 6;
        float sv[6];
        const float2* sp = reinterpret_cast<const float2*>(Sin + m * 6);
        #pragma unroll
        for (int q = 0; q < 3; ++q) { float2 v = sp[q]; sv[q*2] = v.x; sv[q*2+1] = v.y; }
        float acc[6];
        #pragma unroll
        for (int r = 0; r < 6; ++r) {
            const float2* tp = reinterpret_cast<const float2*>(T + a * SA + r * SR);
            float s = 0.f;
            #pragma unroll
            for (int q = 0; q < 3; ++q) {
                float2 v = tp[q];
                s = fmaf(sv[q*2], v.x, s); s = fmaf(sv[q*2+1], v.y, s);
            }
            acc[r] = s;
        }
        float2* op = reinterpret_cast<float2*>(Sout + t * 6);
        #pragma unroll
        for (int q = 0; q < 3; ++q) op[q] = make_float2(acc[q*2], acc[q*2+1]);
    }
}

__device__ __forceinline__ float stepX6R1_body(const float* __restrict__ Sin,
                                               float* __restrict__ Sout,
                                               const float* __restrict__ T) {
    const int m = threadIdx.x;
    float ss = 0.f;
    if (m < 216) {
        float sv[6];
        const float2* sp = reinterpret_cast<const float2*>(Sin + m * 6);
        #pragma unroll
        for (int q = 0; q < 3; ++q) { float2 v = sp[q]; sv[q*2] = v.x; sv[q*2+1] = v.y; }
        float tt[36];
        const float4* p = reinterpret_cast<const float4*>(T);
        #pragma unroll
        for (int q = 0; q < 9; ++q) { float4 v = p[q]; tt[q*4]=v.x; tt[q*4+1]=v.y; tt[q*4+2]=v.z; tt[q*4+3]=v.w; }
        float acc[6];
        #pragma unroll
        for (int a = 0; a < 6; ++a) {
            float s = 0.f;
            #pragma unroll
            for (int x = 0; x < 6; ++x) s = fmaf(sv[x], tt[a*6+x], s);
            acc[a] = s;
            ss = fmaf(s, s, ss);
        }
        float2* op = reinterpret_cast<float2*>(Sout + m * 6);
        #pragma unroll
        for (int q = 0; q < 3; ++q) op[q] = make_float2(acc[q*2], acc[q*2+1]);
    }
    return ss;
}

// X=1 insert: out[m*36+a*6+r] = sum_u Sin[u*216+m]*T[u*36+r*6+a]
__device__ __forceinline__ void insert_body(const float* __restrict__ Sin,
                                            float* __restrict__ Sout,
                                            const float* __restrict__ T) {
    const int m = threadIdx.x;
    if (m < 216) {
        float acc[36];
        #pragma unroll
        for (int i = 0; i < 36; ++i) acc[i] = 0.f;
        #pragma unroll
        for (int u = 0; u < 6; ++u) {
            const float s = Sin[u * 216 + m];
            const float4* p = reinterpret_cast<const float4*>(T + u * 36);
            #pragma unroll
            for (int q = 0; q < 9; ++q) {
                float4 v = p[q];
                #pragma unroll
                for (int j = 0; j < 4; ++j) {
                    const int e = q * 4 + j;
                    const int r = e / 6, a = e % 6;
                    const float val = (j == 0) ? v.x : (j == 1) ? v.y : (j == 2) ? v.z : v.w;
                    acc[a * 6 + r] = fmaf(s, val, acc[a * 6 + r]);
                }
            }
        }
        float4* op = reinterpret_cast<float4*>(Sout + m * 36);
        #pragma unroll
        for (int q = 0; q < 9; ++q) op[q] = make_float4(acc[q*4], acc[q*4+1], acc[q*4+2], acc[q*4+3]);
    }
}

__device__ __forceinline__ float contract_u_body(const float* __restrict__ Sin,
                                                 float* __restrict__ Sout,
                                                 const float* __restrict__ T) {
    const int m = threadIdx.x;
    float ss = 0.f;
    if (m < 216) {
        float acc[6] = {0.f, 0.f, 0.f, 0.f, 0.f, 0.f};
        #pragma unroll
        for (int u = 0; u < 6; ++u) {
            float sv[6];
            const float2* sp = reinterpret_cast<const float2*>(Sin + (u * 216 + m) * 6);
            #pragma unroll
            for (int q = 0; q < 3; ++q) { float2 v = sp[q]; sv[q*2] = v.x; sv[q*2+1] = v.y; }
            #pragma unroll
            for (int a = 0; a < 6; ++a) {
                const float2* tp = reinterpret_cast<const float2*>(T + u * 36 + a * 6);
                float s = acc[a];
                #pragma unroll
                for (int q = 0; q < 3; ++q) {
                    float2 v = tp[q];
                    s = fmaf(sv[q*2], v.x, s); s = fmaf(sv[q*2+1], v.y, s);
                }
                acc[a] = s;
            }
        }
        #pragma unroll
        for (int a = 0; a < 6; ++a) ss = fmaf(acc[a], acc[a], ss);
        float2* op = reinterpret_cast<float2*>(Sout + m * 6);
        #pragma unroll
        for (int q = 0; q < 3; ++q) op[q] = make_float2(acc[q*2], acc[q*2+1]);
    }
    return ss;
}

__device__ __forceinline__ void cstep_full_tt_body(const float* __restrict__ Sin,
                                                   float* __restrict__ Sout,
                                                   const float* __restrict__ TT) {
    const int t = threadIdx.x;
    if (t < 216) {
        const int mg = t / 6, a = t % 6;
        u64 acc[18];
        #pragma unroll
        for (int i = 0; i < 18; ++i) acc[i] = 0ull;
        #pragma unroll
        for (int u = 0; u < 6; ++u) {
            const float* sb = Sin + u * 1296 + mg * 36;
            const ulonglong2* tb = reinterpret_cast<const ulonglong2*>(TT + u * 216 + a * 36);
            #pragma unroll
            for (int xp = 0; xp < 3; ++xp) {
                ulonglong2 w0 = tb[xp*3], w1 = tb[xp*3+1], w2 = tb[xp*3+2];
                const u64 te0 = w0.x, te1 = w0.y, te2 = w1.x;
                const u64 to0 = w1.y, to1 = w2.x, to2 = w2.y;
                #pragma unroll
                for (int mi = 0; mi < 6; ++mi) {
                    const float2 sv = *reinterpret_cast<const float2*>(sb + mi * 6 + xp * 2);
                    const u64 s0 = pk2(sv.x, sv.x);
                    const u64 s1 = pk2(sv.y, sv.y);
                    fma2(acc[mi*3+0], s0, te0); fma2(acc[mi*3+1], s0, te1); fma2(acc[mi*3+2], s0, te2);
                    fma2(acc[mi*3+0], s1, to0); fma2(acc[mi*3+1], s1, to1); fma2(acc[mi*3+2], s1, to2);
                }
            }
        }
        float* ob = Sout + mg * 216 + a * 6;
        #pragma unroll
        for (int mi = 0; mi < 6; ++mi) {
            u64* op = reinterpret_cast<u64*>(ob + mi * 36);
            op[0] = acc[mi*3]; op[1] = acc[mi*3+1]; op[2] = acc[mi*3+2];
        }
    }
}

__global__ void __launch_bounds__(NT, 3)
peps_kernel(const float* __restrict__ inp, const float* __restrict__ peps,
            const float* __restrict__ pc, float* __restrict__ out) {
    extern __shared__ __align__(16) char smem_raw[];
    Smem& S = *reinterpret_cast<Smem*>(smem_raw);
    const int batch = blockIdx.x;
    const float* xs = inp + batch * 32;
    float* const ENVTOP = S.Sb + 6480;
    float* const NA = S.node;         // slot A
    float* const NB = S.node + 648;   // slot B
    float* const DOTS = S.node;       // dead at final
    float* const RED = S.red;

    // ---- prefetch N01,N31; inline N00 -> Sa[0:36], N30 -> Sa[3888:3924] ----
    NodeLoad<0, 1, 1, 6, 6, 6> stA; stA.load(peps, xs);
    NodeLoad<3, 1, 6, 6, 1, 6> stB; stB.load(peps, xs);
    if (threadIdx.x < 36) {
        const int d = threadIdx.x / 6, r = threadIdx.x % 6;
        const int g = (r * 6 + d) * 6;
        const float* T0 = peps;
        const float* T1 = T0 + 1296;
        S.Sa[threadIdx.x] = fmaf(xs[0], __ldg(T0 + g), xs[1] * __ldg(T1 + g));
    } else if (threadIdx.x >= 64 && threadIdx.x < 100) {
        const int tt = threadIdx.x - 64;
        const int g = tt * 36;                      // (u*6+r)*36
        const float* T0 = peps + (size_t)24 * 1296; // (3,0) pair
        const float* T1 = T0 + 1296;
        S.Sa[3888 + tt] = fmaf(xs[24], __ldg(T0 + g), xs[25] * __ldg(T1 + g));
    }
    __syncthreads();

    // ============ fused row0 + row3 boundary chains ============
    stA.store(NA); stB.store(NB);
    NodeLoad<0, 2, 1, 6, 6, 6> stA2; stA2.load(peps, xs);
    NodeLoad<3, 2, 6, 6, 1, 6> stB2; stB2.load(peps, xs);
    __syncthreads();
    step6_body<6, 36>(S.Sa, S.Sb, NA);               // row0 -> Sb[0:216]
    step6_body<36, 6>(S.Sa + 3888, S.Sb + 3888, NB); // row3 -> Sb[3888:4104]
    __syncthreads();
    stA2.store(NA); stB2.store(NB);
    NodeLoad<0, 3, 1, 1, 6, 6> stA3; stA3.load(peps, xs);
    NodeLoad<3, 3, 6, 1, 1, 6> stB3; stB3.load(peps, xs);
    __syncthreads();
    step36_body<6, 36>(S.Sb, S.Sa, NA);
    step36_body<36, 6>(S.Sb + 3888, S.Sa + 3888, NB);
    __syncthreads();
    stA3.store(NA); stB3.store(NB);
    NodeLoad<1, 0, 6, 6, 6, 1> st10; st10.load(peps, xs);
    __syncthreads();
    float ss0 = stepX6R1_body(S.Sa, S.Sb, NA);           // row0 env -> Sb[0:1296]
    float ss3 = stepX6R1_body(S.Sa + 3888, S.envbot, NB);// env_bot -> envbot
    const float2 iv = block_reduce2(ss0, ss3, RED);
    const float inv0 = rsqrtf(iv.x);
    const float inv3 = rsqrtf(iv.y);

    // ============ Row 1 ============
    st10.store_scaled(NA, inv0);                         // range-keeper folded in
    NodeLoadTT<1, 1> st11; st11.load(peps, xs);
    __syncthreads();
    insert_body(S.Sb, S.Sa, NA);                         // -> 7776
    __syncthreads();
    st11.store(S.node);
    NodeLoadTT<1, 2> st12; st12.load(peps, xs);
    __syncthreads();
    cstep_full_tt_body(S.Sa, S.Sb, S.node);              // N11
    __syncthreads();
    st12.store(S.node);
    NodeLoad<1, 3, 6, 1, 6, 6> st13; st13.load(peps, xs);
    __syncthreads();
    cstep_full_tt_body(S.Sb, S.Sa, S.node);              // N12
    __syncthreads();
    st13.store(NA);
    NodeLoad<2, 0, 6, 6, 6, 1> st20; st20.load(peps, xs);
    __syncthreads();
    float sst = contract_u_body(S.Sa, ENVTOP, NA);       // env_top (Sb tail)
    const float2 ivt = block_reduce2(sst, 0.f, RED);
    const float inv_top = rsqrtf(ivt.x);

    // ============ Row 2 (j=0,1) ============
    st20.store_scaled(NA, inv_top);                      // range-keeper folded in
    NodeLoadTT<2, 1> st21; st21.load(peps, xs);
    __syncthreads();
    insert_body(ENVTOP, S.Sa, NA);                       // -> 7776
    __syncthreads();
    st21.store(S.node);
    NodeLoad<2, 3, 6, 1, 6, 6> st23; st23.load(peps, xs);
    __syncthreads();
    cstep_full_tt_body(S.Sa, S.Sb, S.node);              // N21 -> S1 in Sb
    __syncthreads();
    st23.store_scaled(NA, inv3);                         // N23, range-keeper folded
    __syncthreads();

    // ============ E step: thread-per-k, FFMA2 over r ============
    // E[k*36 + d2*6 + r2] = sum_d3 envbot[d0,d1,d2,d3]*n23[u3,d3,r2], k=u3*36+d0*6+d1
    {
        const int t = threadIdx.x;
        if (t < 216) {
            const int u3 = t / 36, d0 = (t / 6) % 6, d1 = t % 6;
            u64 acc[18];
            #pragma unroll
            for (int i = 0; i < 18; ++i) acc[i] = 0ull;
            #pragma unroll
            for (int d3 = 0; d3 < 6; ++d3) {
                const u64* np = reinterpret_cast<const u64*>(NA + u3 * 36 + d3 * 6);
                const u64 n0 = np[0], n1 = np[1], n2v = np[2];
                const float* ebp = S.envbot + d0 * 216 + d1 * 36 + d3;
                #pragma unroll
                for (int d2 = 0; d2 < 6; ++d2) {
                    const float e = ebp[d2 * 6];
                    const u64 e2 = pk2(e, e);
                    fma2(acc[d2*3+0], e2, n0); fma2(acc[d2*3+1], e2, n1); fma2(acc[d2*3+2], e2, n2v);
                }
            }
            u64* op = reinterpret_cast<u64*>(S.Sa + t * 36);
            #pragma unroll
            for (int i = 0; i < 18; ++i) op[i] = acc[i];
        }
        __syncthreads();
    }

    // ============ W step: thread-per-(u,d,r), FFMA2 over l ============
    // W[u*216+r*36+d*6+l] = sum_k S1[u*1296+k*6+l] * E[k*36+d*6+r]  -> envbot
    {
        const int t = threadIdx.x;
        if (t < 216) {
            const int u = t / 36, d = (t / 6) % 6, r = t % 6;
            u64 acc0 = 0ull, acc1 = 0ull, acc2v = 0ull;
            const ulonglong2* sp = reinterpret_cast<const ulonglong2*>(S.Sb + u * 1296);
            const float* ep = S.Sa + d * 6 + r;
            #pragma unroll 4
            for (int kk = 0; kk < 108; ++kk) {
                const ulonglong2 q0 = sp[kk*3], q1 = sp[kk*3+1], q2 = sp[kk*3+2];
                const u64 e02 = pk2(ep[kk * 72], ep[kk * 72]);
                const u64 e12 = pk2(ep[kk * 72 + 36], ep[kk * 72 + 36]);
                fma2(acc0, q0.x, e02); fma2(acc1, q0.y, e02); fma2(acc2v, q1.x, e02);
                fma2(acc0, q1.y, e12); fma2(acc1, q2.x, e12); fma2(acc2v, q2.y, e12);
            }
            u64* op = reinterpret_cast<u64*>(S.envbot + u * 216 + r * 36 + d * 6);
            op[0] = acc0; op[1] = acc1; op[2] = acc2v;
        }
        __syncthreads();
    }

    // ============ final: out[o] ∝ sum_p x_p * <Tc[p,o,:], W> ============
    {
        const int w = threadIdx.x >> 5, lane = threadIdx.x & 31;
        const float4* wv = reinterpret_cast<const float4*>(S.envbot);
        for (int po = w; po < 20; po += 8) {
            const float4* tc = reinterpret_cast<const float4*>(pc + (size_t)po * 1296);
            float s = 0.f;
            for (int g = lane; g < 324; g += 32) {
                float4 a = __ldg(tc + g), v = wv[g];
                s = fmaf(a.x, v.x, s); s = fmaf(a.y, v.y, s);
                s = fmaf(a.z, v.z, s); s = fmaf(a.w, v.w, s);
            }
            #pragma unroll
            for (int o = 16; o; o >>= 1) s += __shfl_xor_sync(0xffffffffu, s, o);
            if (lane == 0) DOTS[po] = s;
        }
        __syncthreads();
        if (threadIdx.x == 0) {
            const float x0 = xs[(2 * 4 + 2) * 2 + 0];
            const float x1 = xs[(2 * 4 + 2) * 2 + 1];
            float raw[10];
            float m = 0.f;
            #pragma unroll
            for (int o = 0; o < 10; ++o) {
                raw[o] = fmaf(x0, DOTS[o], x1 * DOTS[10 + o]);
                m = fmaxf(m, fabsf(raw[o]));
            }
            const float im = 1.0f / m;
            float ss = 0.f;
            #pragma unroll
            for (int o = 0; o < 10; ++o) { const float v = raw[o] * im; ss += v * v; }
            const float inv = rsqrtf(ss) * im;
            #pragma unroll
            for (int o = 0; o < 10; ++o) out[batch * 10 + o] = raw[o] * inv;
        }
    }
}

extern "C" void kernel_launch(void* const* d_in, const int* in_sizes, int n_in,
                              void* d_out, int out_size) {
    const float *inp = nullptr, *peps = nullptr, *pc = nullptr;
    for (int i = 0; i < n_in; ++i) {
        if (in_sizes[i] == 1024 * 4 * 4 * 2)      inp  = (const float*)d_in[i];
        else if (in_sizes[i] == 4 * 4 * 2 * 1296) peps = (const float*)d_in[i];
        else if (in_sizes[i] == 2 * 10 * 1296)    pc   = (const float*)d_in[i];
    }
    const int smem = (int)sizeof(Smem);   // 72,640 B -> 3 blocks/SM
    cudaFuncSetAttribute(peps_kernel, cudaFuncAttributeMaxDynamicSharedMemorySize, smem);
    peps_kernel<<<1024, NT, smem>>>(inp, peps, pc, (float*)d_out);
}